// round 7
// baseline (speedup 1.0000x reference)
#include <cuda_runtime.h>
#include <cuda_fp16.h>

// Fused AA max-pool: up2+FIR7 -> maxpool5x5 s1 -> FIR7+down4.
// One CTA = TWO (n,c) images x 8 output rows, 256 threads (8 warps).
//  s1+s2 FUSED: vertical up-FIR in registers from global, horizontal up-FIR
//               via warp shuffles (4-lane column halo per warp), rolling
//               5-row max -> sM (half2, col-pair packed). No sA at all.
//  s3: SIMD 5-col max (hmax2/prmt) + vertical down-FIR (fp32) -> sD
//  s4: horizontal down-FIR (float4 loads) -> out

#define TI   8
#define WIN  112
#define WMW  120                 // sM row stride (half2 words); word j = cols (2j-4,2j-3)
#define NRM  35
#define M_WORDS (NRM*WMW)        // 4200
#define WDS  232                 // sD: col s at idx s+4
#define HOUT 56
#define WOUT 56
#define NTHREADS 256

#define OFF_M 0                          // 2 imgs x 4200 words
#define OFF_D (2*M_WORDS)                // 2 imgs x 8*232 floats
#define SMEM_WORDS (OFF_D + 2*(TI*WDS))  // 12112 words = 48448 B -> 4 CTAs/SM

__device__ __forceinline__ __half2 h2shift(__half2 a, __half2 b) {
    unsigned r = __byte_perm(*(unsigned*)&a, *(unsigned*)&b, 0x5432);
    return *(__half2*)&r;
}

__global__ void __launch_bounds__(NTHREADS, 4)
aamaxpool_fused_kernel(const float* __restrict__ x,
                       const float* __restrict__ fpre,
                       const float* __restrict__ fpost,
                       float* __restrict__ out)
{
    extern __shared__ float sm[];
    unsigned* sMh = (unsigned*)sm + OFF_M;
    float*    sD  = sm + OFF_D;

    const int t  = threadIdx.x;
    const int i0 = blockIdx.x * TI;
    const int nc0 = 2 * blockIdx.y;
    const int in_row0 = 2*i0 - 3;
    const int u0 = 4*i0 - 4;
    const int r0 = 4*i0 - 3;
    const float NEG_INF = __int_as_float(0xff800000);

    const float f0=__ldg(fpre+0), f1=__ldg(fpre+1), f2=__ldg(fpre+2),
                f3=__ldg(fpre+3), f4=__ldg(fpre+4), f5=__ldg(fpre+5),
                f6=__ldg(fpre+6);
    float g[7];
#pragma unroll
    for (int i = 0; i < 7; i++) g[i] = __ldg(fpost + i);

    // ---- sM -inf pads: words {0,1,114,115} x 35 rows x 2 imgs ----
    for (int idx = t; idx < 280; idx += NTHREADS) {
        int im = idx / 140, rem = idx - 140*im;
        int lr = rem >> 2, k = rem & 3;
        sMh[im*M_WORDS + lr*WMW + (k < 2 ? k : 112 + k)] = 0xFC00FC00u;
    }
    // ---- sD left zero pads: idx 0..3 x 8 rows x 2 imgs ----
    if (t < 64) {
        int im = t >> 5, rem = t & 31;
        sD[im*(TI*WDS) + (rem >> 2)*WDS + (rem & 3)] = 0.f;
    }

    // ---- fused stage 1+2: vertical FIR (regs) + shfl horizontal FIR + 5-row max ----
    {
        const int wid = t >> 5, lane = t & 31;
        const int img = wid >> 2;                // warps 0-3 img0, 4-7 img1
        const int wk  = wid & 3;
        const int c   = 28*wk - 1 + lane;        // A col, -1..114
        const bool real  = ((unsigned)c < 112u);
        const bool emits = (lane >= 1) && (lane <= 28);   // c in [28wk, 28wk+27]
        const float* col = x + (size_t)(nc0 + img)*(WIN*WIN) + (real ? c : 0);
        unsigned* mrow = sMh + img*M_WORDS + (c + 2);
        const int vlo = (0 - u0) > 0 ? (0 - u0) : 0;
        const int vhi = (224 - u0) < 39 ? (224 - u0) : 39;

        float x0, x1, x2;
        { int r = in_row0;     x0 = (real && r>=0 && r<WIN) ? col[r*WIN] : 0.f; }
        { int r = in_row0 + 1; x1 = (real && r>=0 && r<WIN) ? col[r*WIN] : 0.f; }
        { int r = in_row0 + 2; x2 = (real && r>=0 && r<WIN) ? col[r*WIN] : 0.f; }
        float e0=0,e1=0,e2=0,e3=0,e4=0;
        float o0=0,o1=0,o2=0,o3=0,o4=0;

#pragma unroll
        for (int q = 0; q < 20; q++) {
            int r = in_row0 + q + 3;
            float x3 = (real && r>=0 && r<WIN) ? col[r*WIN] : 0.f;
            float ae = f1*x0 + f3*x1 + f5*x2;                 // A row 2q
            float ao = f0*x0 + f2*x1 + f4*x2 + f6*x3;         // A row 2q+1
#pragma unroll
            for (int hp = 0; hp < 2; hp++) {
                const int lu = 2*q + hp;
                if (lu >= 39) break;
                float a1 = hp ? ao : ae;
                float a0 = __shfl_up_sync  (0xffffffffu, a1, 1);
                float a2 = __shfl_down_sync(0xffffffffu, a1, 1);
                float a3 = __shfl_down_sync(0xffffffffu, a1, 2);
                float be = f1*a0 + f3*a1 + f5*a2;             // col 2c
                float bo = f0*a0 + f2*a1 + f4*a2 + f6*a3;     // col 2c+1
                bool valid = (lu >= vlo) && (lu < vhi);
                be = valid ? be : NEG_INF;
                bo = valid ? bo : NEG_INF;
                e0=e1; e1=e2; e2=e3; e3=e4; e4=be;
                o0=o1; o1=o2; o2=o3; o3=o4; o4=bo;
                if (lu >= 4 && emits) {
                    float me = fmaxf(fmaxf(fmaxf(e0,e1), fmaxf(e2,e3)), e4);
                    float mo = fmaxf(fmaxf(fmaxf(o0,o1), fmaxf(o2,o3)), o4);
                    __half2 h = __floats2half2_rn(me, mo);
                    mrow[(lu - 4)*WMW] = *(unsigned*)&h;
                }
            }
            x0 = x1; x1 = x2; x2 = x3;
        }
    }
    __syncthreads();

    // ---- stage 3: SIMD 5-col window max + vertical FIR (li-pairs) -> sD ----
    {
        const int img = t >> 7;                // threads 0-127 img0, 128-255 img1
        const int tl  = t & 127;
        if (tl < 112) {
            const int q  = tl % 28;            // cols s = 8q..8q+7
            const int lp = tl / 28;            // output rows 2lp, 2lp+1
            const unsigned* Mi = sMh + img*M_WORDS;
            float d0[8] = {0,0,0,0,0,0,0,0};
            float d1[8] = {0,0,0,0,0,0,0,0};
#pragma unroll
            for (int rr = 0; rr < 11; rr++) {
                const int lc = 8*lp + rr;
                const int rg = r0 + lc;
                if (rg >= 0 && rg < 222) {
                    const unsigned* Wp = Mi + lc*WMW + 4*q;
                    uint4 u0v = *reinterpret_cast<const uint4*>(Wp);
                    uint4 u1v = *reinterpret_cast<const uint4*>(Wp + 4);
                    __half2 H0=*(__half2*)&u0v.x, H1=*(__half2*)&u0v.y,
                            H2=*(__half2*)&u0v.z, H3=*(__half2*)&u0v.w,
                            H4=*(__half2*)&u1v.x, H5=*(__half2*)&u1v.y,
                            H6=*(__half2*)&u1v.z, H7=*(__half2*)&u1v.w;
                    __half2 S1=h2shift(H1,H2), S2=h2shift(H2,H3), S3=h2shift(H3,H4),
                            S4=h2shift(H4,H5), S5=h2shift(H5,H6), S6=h2shift(H6,H7);
                    __half2 Z2=__hmax2(H2,S2), Z3=__hmax2(H3,S3), Z4=__hmax2(H4,S4),
                            Z5=__hmax2(H5,S5), Z6=__hmax2(H6,S6);
                    __half2 O0=__hmax2(S1,__hmax2(Z2,Z3));
                    __half2 O1=__hmax2(S2,__hmax2(Z3,Z4));
                    __half2 O2=__hmax2(S3,__hmax2(Z4,Z5));
                    __half2 O3=__hmax2(S4,__hmax2(Z5,Z6));
                    float2 c01=__half22float2(O0), c23=__half22float2(O1),
                           c45=__half22float2(O2), c67=__half22float2(O3);
                    float wv[8] = {c01.x,c01.y,c23.x,c23.y,c45.x,c45.y,c67.x,c67.y};
                    if (rr <= 6) {
                        float ga = g[rr];
#pragma unroll
                        for (int j = 0; j < 8; j++) d0[j] += ga * wv[j];
                    }
                    if (rr >= 4) {
                        float gb = g[rr - 4];
#pragma unroll
                        for (int j = 0; j < 8; j++) d1[j] += gb * wv[j];
                    }
                }
            }
            if (q == 27) { d0[6]=0.f; d0[7]=0.f; d1[6]=0.f; d1[7]=0.f; }
            float* Di = sD + img*(TI*WDS);
            float* P0 = Di + (2*lp  )*WDS + 8*q + 4;
            float* P1 = Di + (2*lp+1)*WDS + 8*q + 4;
            *reinterpret_cast<float4*>(P0)     = make_float4(d0[0],d0[1],d0[2],d0[3]);
            *reinterpret_cast<float4*>(P0 + 4) = make_float4(d0[4],d0[5],d0[6],d0[7]);
            *reinterpret_cast<float4*>(P1)     = make_float4(d1[0],d1[1],d1[2],d1[3]);
            *reinterpret_cast<float4*>(P1 + 4) = make_float4(d1[4],d1[5],d1[6],d1[7]);
        }
    }
    __syncthreads();

    // ---- stage 4: horizontal down-FIR (aligned float4 loads) -> out ----
#pragma unroll
    for (int k = 0; k < 4; k++) {
        int gid = t + k*NTHREADS;              // 0..895 = 2 imgs x 8 rows x 56
        if (gid < 896) {
            int im  = gid / 448;
            int rem = gid - 448*im;
            int li  = rem / 56, j = rem - 56*li;
            const float* Dr = sD + im*(TI*WDS) + li*WDS + 4*j;
            float4 va = *reinterpret_cast<const float4*>(Dr);
            float4 vb = *reinterpret_cast<const float4*>(Dr + 4);
            float acc = g[0]*va.y + g[1]*va.z + g[2]*va.w
                      + g[3]*vb.x + g[4]*vb.y + g[5]*vb.z + g[6]*vb.w;
            out[(size_t)(nc0 + im)*(HOUT*WOUT) + (i0 + li)*WOUT + j] = acc;
        }
    }
}

extern "C" void kernel_launch(void* const* d_in, const int* in_sizes, int n_in,
                              void* d_out, int out_size)
{
    const float* x     = (const float*)d_in[0];   // (32,64,112,112)
    const float* fpre  = (const float*)d_in[1];   // (7,)
    const float* fpost = (const float*)d_in[2];   // (7,)
    float* out = (float*)d_out;                   // (32,64,56,56)

    const size_t smem_bytes = SMEM_WORDS * sizeof(float); // 48448
    cudaFuncSetAttribute(aamaxpool_fused_kernel,
                         cudaFuncAttributeMaxDynamicSharedMemorySize,
                         (int)smem_bytes);

    dim3 grid(HOUT / TI, 32 * 64 / 2);   // 7 strips x 1024 image-pairs
    aamaxpool_fused_kernel<<<grid, NTHREADS, smem_bytes>>>(x, fpre, fpost, out);
}

// round 8
// speedup vs baseline: 1.1240x; 1.1240x over previous
#include <cuda_runtime.h>
#include <cuda_fp16.h>

// Fused AA max-pool: up2+FIR7 -> maxpool5x5 s1 -> FIR7+down4.
// One CTA = TWO (n,c) images x 8 output rows, 256 threads.
//  s1: global -> vertical up-FIR (polyphase stream) -> sA (fp32)   [t<224 dense]
//  s2: horizontal up-FIR (fp32) + rolling 5-row max in HALF2 -> sM [t<224 dense]
//  s3: SIMD 5-col max + vertical down-FIR + horizontal down-FIR via 6 shuffles
//      -> direct global store. One warp per (img, row-pair); no sD, no stage 4.

#define TI   8
#define WIN  112
#define WAS  116                 // sA: col c at idx c+1 (c in [-1,114])
#define NRA  40
#define A_FLOATS (NRA*WAS)       // 4640
#define WMW  120                 // sM row stride (half2 words); word j = cols (2j-4,2j-3)
#define NRM  35
#define M_WORDS (NRM*WMW)        // 4200
#define HOUT 56
#define WOUT 56
#define NTHREADS 256

#define OFF_M 0                          // 2 imgs x 4200 words
#define OFF_A (2*M_WORDS)                // 2 imgs x 4640 floats
#define SMEM_WORDS (OFF_A + 2*A_FLOATS)  // 17680 words = 70720 B -> 3 CTAs/SM

__device__ __forceinline__ __half2 h2shift(__half2 a, __half2 b) {
    unsigned r = __byte_perm(*(unsigned*)&a, *(unsigned*)&b, 0x5432);
    return *(__half2*)&r;
}

__global__ void __launch_bounds__(NTHREADS, 3)
aamaxpool_fused_kernel(const float* __restrict__ x,
                       const float* __restrict__ fpre,
                       const float* __restrict__ fpost,
                       float* __restrict__ out)
{
    extern __shared__ float sm[];
    unsigned* sMh = (unsigned*)sm + OFF_M;
    float*    sA  = sm + OFF_A;

    const int t  = threadIdx.x;
    const int i0 = blockIdx.x * TI;
    const int nc0 = 2 * blockIdx.y;
    const int in_row0 = 2*i0 - 3;
    const int u0 = 4*i0 - 4;
    const int r0 = 4*i0 - 3;
    const unsigned NEG2U = 0xFC00FC00u;   // half2(-inf,-inf)

    const float f0=__ldg(fpre+0), f1=__ldg(fpre+1), f2=__ldg(fpre+2),
                f3=__ldg(fpre+3), f4=__ldg(fpre+4), f5=__ldg(fpre+5),
                f6=__ldg(fpre+6);
    float g[7];
#pragma unroll
    for (int i = 0; i < 7; i++) g[i] = __ldg(fpost + i);

    // ---- sM -inf pads: words {0,1,114,115} x 35 rows x 2 imgs ----
    for (int idx = t; idx < 280; idx += NTHREADS) {
        int im = idx / 140, rem = idx - 140*im;
        int lr = rem >> 2, k = rem & 3;
        sMh[im*M_WORDS + lr*WMW + (k < 2 ? k : 112 + k)] = NEG2U;
    }

    if (t < 224) {
        const int img = t / 112;
        const int w   = t - 112*img;

        // ---- stage 1: vertical up-2 FIR -> sA, stream 23 input rows ----
        {
            const float* col = x + (size_t)(nc0 + img) * (WIN*WIN) + w;
            float* sAc = sA + img*A_FLOATS + (w + 1);
            float x0, x1, x2;
            { int r = in_row0;     x0 = (r>=0 && r<WIN) ? col[r*WIN] : 0.f; }
            { int r = in_row0 + 1; x1 = (r>=0 && r<WIN) ? col[r*WIN] : 0.f; }
            { int r = in_row0 + 2; x2 = (r>=0 && r<WIN) ? col[r*WIN] : 0.f; }
#pragma unroll
            for (int q = 0; q < 20; q++) {
                int r = in_row0 + q + 3;
                float x3 = (r>=0 && r<WIN) ? col[r*WIN] : 0.f;
                sAc[(2*q  )*WAS] = f1*x0 + f3*x1 + f5*x2;
                sAc[(2*q+1)*WAS] = f0*x0 + f2*x1 + f4*x2 + f6*x3;
                x0 = x1; x1 = x2; x2 = x3;
            }
        }
        // sA halo zeros: idx {0,113,114} x 40 rows x 2 imgs = 240
        for (int idx = t; idx < 240; idx += 224) {
            int im = idx / 120, rem = idx - 120*im;
            int lu = rem / 3, k = rem - 3*lu;
            sA[im*A_FLOATS + lu*WAS + (k == 0 ? 0 : 112 + k)] = 0.f;
        }
    }
    __syncthreads();

    // ---- stage 2: horizontal up-2 FIR (fp32) + half2 rolling 5-row max -> sM ----
    if (t < 224) {
        const int img = t / 112;
        const int w   = t - 112*img;
        const float* ap = sA + img*A_FLOATS + w;       // a[k] = A[w-1+k]
        unsigned* mcol = sMh + img*M_WORDS + (w + 2);
        const int vlo = (0 - u0) > 0 ? (0 - u0) : 0;
        const int vhi = (224 - u0) < 39 ? (224 - u0) : 39;
        const __half2 NEG2 = *(const __half2*)&NEG2U;
        __half2 m0=NEG2, m1=NEG2, m2=NEG2, m3=NEG2, m4=NEG2;
#pragma unroll
        for (int lu = 0; lu < 39; lu++) {
            const float* a = ap + lu*WAS;
            float a0 = a[0], a1 = a[1], a2 = a[2], a3 = a[3];
            float be = f1*a0 + f3*a1 + f5*a2;          // col 2w
            float bo = f0*a0 + f2*a1 + f4*a2 + f6*a3;  // col 2w+1
            __half2 h = __floats2half2_rn(be, bo);
            bool valid = (lu >= vlo) && (lu < vhi);
            h = valid ? h : NEG2;                      // -inf pad for maxpool
            m0=m1; m1=m2; m2=m3; m3=m4; m4=h;
            if (lu >= 4) {
                __half2 mx = __hmax2(__hmax2(__hmax2(m0,m1), __hmax2(m2,m3)), m4);
                mcol[(lu - 4)*WMW] = *(unsigned*)&mx;
            }
        }
    }
    __syncthreads();

    // ---- stage 3: SIMD 5-col max + vertical FIR + shfl horizontal FIR -> out ----
    {
        const int wid = t >> 5, lane = t & 31;
        const int img = wid >> 2;                  // warps 0-3 img0, 4-7 img1
        const int lp  = wid & 3;                   // output rows 2lp, 2lp+1
        const int q   = (lane < 28) ? lane : 27;   // cols s = 8q..8q+7 (clamped dup)
        const unsigned* Mi = sMh + img*M_WORDS;
        float d0[8] = {0,0,0,0,0,0,0,0};
        float d1[8] = {0,0,0,0,0,0,0,0};
#pragma unroll
        for (int rr = 0; rr < 11; rr++) {
            const int lc = 8*lp + rr;
            const int rg = r0 + lc;
            if (rg >= 0 && rg < 222) {             // uniform across warp
                const unsigned* Wp = Mi + lc*WMW + 4*q;
                uint4 u0v = *reinterpret_cast<const uint4*>(Wp);
                uint4 u1v = *reinterpret_cast<const uint4*>(Wp + 4);
                __half2 H0=*(__half2*)&u0v.x, H1=*(__half2*)&u0v.y,
                        H2=*(__half2*)&u0v.z, H3=*(__half2*)&u0v.w,
                        H4=*(__half2*)&u1v.x, H5=*(__half2*)&u1v.y,
                        H6=*(__half2*)&u1v.z, H7=*(__half2*)&u1v.w;
                __half2 S1=h2shift(H1,H2), S2=h2shift(H2,H3), S3=h2shift(H3,H4),
                        S4=h2shift(H4,H5), S5=h2shift(H5,H6), S6=h2shift(H6,H7);
                __half2 Z2=__hmax2(H2,S2), Z3=__hmax2(H3,S3), Z4=__hmax2(H4,S4),
                        Z5=__hmax2(H5,S5), Z6=__hmax2(H6,S6);
                __half2 O0=__hmax2(S1,__hmax2(Z2,Z3));
                __half2 O1=__hmax2(S2,__hmax2(Z3,Z4));
                __half2 O2=__hmax2(S3,__hmax2(Z4,Z5));
                __half2 O3=__hmax2(S4,__hmax2(Z5,Z6));
                float2 c01=__half22float2(O0), c23=__half22float2(O1),
                       c45=__half22float2(O2), c67=__half22float2(O3);
                float wv[8] = {c01.x,c01.y,c23.x,c23.y,c45.x,c45.y,c67.x,c67.y};
                if (rr <= 6) {
                    float ga = g[rr];
#pragma unroll
                    for (int j = 0; j < 8; j++) d0[j] += ga * wv[j];
                }
                if (rr >= 4) {
                    float gb = g[rr - 4];
#pragma unroll
                    for (int j = 0; j < 8; j++) d1[j] += gb * wv[j];
                }
            }
        }
        if (q == 27) { d0[6]=0.f; d0[7]=0.f; d1[6]=0.f; d1[7]=0.f; }  // D[222],D[223]=0

        // horizontal down-FIR: neighbor's D cols 8q-3..8q-1 via shfl_up
        float n5a = __shfl_up_sync(0xffffffffu, d0[5], 1);
        float n6a = __shfl_up_sync(0xffffffffu, d0[6], 1);
        float n7a = __shfl_up_sync(0xffffffffu, d0[7], 1);
        float n5b = __shfl_up_sync(0xffffffffu, d1[5], 1);
        float n6b = __shfl_up_sync(0xffffffffu, d1[6], 1);
        float n7b = __shfl_up_sync(0xffffffffu, d1[7], 1);
        if (q == 0) { n5a=0.f; n6a=0.f; n7a=0.f; n5b=0.f; n6b=0.f; n7b=0.f; }

        // j=2q  : D[8q-3..8q+3] = n5,n6,n7,d0..d3
        // j=2q+1: D[8q+1..8q+7] = d1..d7
        float oe0 = g[0]*n5a + g[1]*n6a + g[2]*n7a
                  + g[3]*d0[0] + g[4]*d0[1] + g[5]*d0[2] + g[6]*d0[3];
        float oo0 = g[0]*d0[1] + g[1]*d0[2] + g[2]*d0[3] + g[3]*d0[4]
                  + g[4]*d0[5] + g[5]*d0[6] + g[6]*d0[7];
        float oe1 = g[0]*n5b + g[1]*n6b + g[2]*n7b
                  + g[3]*d1[0] + g[4]*d1[1] + g[5]*d1[2] + g[6]*d1[3];
        float oo1 = g[0]*d1[1] + g[1]*d1[2] + g[2]*d1[3] + g[3]*d1[4]
                  + g[4]*d1[5] + g[5]*d1[6] + g[6]*d1[7];

        if (lane < 28) {
            float* ob = out + (size_t)(nc0 + img)*(HOUT*WOUT)
                            + (size_t)(i0 + 2*lp)*WOUT + 2*q;
            *reinterpret_cast<float2*>(ob)        = make_float2(oe0, oo0);
            *reinterpret_cast<float2*>(ob + WOUT) = make_float2(oe1, oo1);
        }
    }
}

extern "C" void kernel_launch(void* const* d_in, const int* in_sizes, int n_in,
                              void* d_out, int out_size)
{
    const float* x     = (const float*)d_in[0];   // (32,64,112,112)
    const float* fpre  = (const float*)d_in[1];   // (7,)
    const float* fpost = (const float*)d_in[2];   // (7,)
    float* out = (float*)d_out;                   // (32,64,56,56)

    const size_t smem_bytes = SMEM_WORDS * sizeof(float); // 70720
    cudaFuncSetAttribute(aamaxpool_fused_kernel,
                         cudaFuncAttributeMaxDynamicSharedMemorySize,
                         (int)smem_bytes);

    dim3 grid(HOUT / TI, 32 * 64 / 2);   // 7 strips x 1024 image-pairs
    aamaxpool_fused_kernel<<<grid, NTHREADS, smem_bytes>>>(x, fpre, fpost, out);
}

// round 9
// speedup vs baseline: 1.4506x; 1.2906x over previous
#include <cuda_runtime.h>
#include <cuda_fp16.h>

// Fused AA max-pool: up2+FIR7 -> maxpool5x5 s1 -> FIR7+down4.
// One CTA = TWO (n,c) images x 8 output rows, 256 threads.
// Row-pair half2 packing through the whole pipeline:
//  s1: vertical up-FIR (fp32 regs) -> sA2 half2 pack (rows 2q,2q+1) [t<224]
//  s2: horizontal up-FIR in HFMA2 (2 rows/iter) + pack rolling 5-row max
//      -> sM2 half2 (M rows 2j,2j+1 per word), STS.64 col-pairs      [t<224]
//  s3: SIMD 5-col max on packs + vertical FIR (static taps) + shfl
//      horizontal FIR -> direct global store. Warp per (img,row-pair4).
// sM column words are bit2-XOR swizzled for conflict-free LDS.128.

#define WIN  112
#define TI   8
#define WAS  116                 // sA2: col c at word c+1 (c in [-1,113])
#define PA   20                  // A packs (rows 0..39)
#define A_WORDS (PA*WAS)         // 2320
#define WMS2 232                 // sM2 row stride (words); col v at word v+4
#define PM   18                  // M packs (rows 0..35)
#define M_WORDS (PM*WMS2)        // 4176
#define HOUT 56
#define WOUT 56
#define NTHREADS 256

#define OFF_M 0                          // 2 imgs x 4176 words
#define OFF_A (2*M_WORDS)                // 2 imgs x 2320 words
#define SMEM_WORDS (OFF_A + 2*A_WORDS)   // 12992 words = 51968 B -> 4 CTAs/SM

__device__ __forceinline__ int swz(int c) { return c ^ (((c >> 5) & 1) << 2); }

__device__ __forceinline__ __half2 h2shift(__half2 a, __half2 b) {
    unsigned r = __byte_perm(*(unsigned*)&a, *(unsigned*)&b, 0x5432);
    return *(__half2*)&r;
}

__global__ void __launch_bounds__(NTHREADS, 4)
aamaxpool_fused_kernel(const float* __restrict__ x,
                       const float* __restrict__ fpre,
                       const float* __restrict__ fpost,
                       float* __restrict__ out)
{
    extern __shared__ unsigned smu[];
    unsigned* sMh = smu + OFF_M;
    unsigned* sA2 = smu + OFF_A;

    const int t  = threadIdx.x;
    const int i0 = blockIdx.x * TI;
    const int nc0 = 2 * blockIdx.y;
    const int in_row0 = 2*i0 - 3;
    const int u0 = 4*i0 - 4;
    const int r0 = 4*i0 - 3;
    const unsigned NEG2U = 0xFC00FC00u;
    const __half2 NEG2 = *(const __half2*)&NEG2U;

    const float f0=__ldg(fpre+0), f1=__ldg(fpre+1), f2=__ldg(fpre+2),
                f3=__ldg(fpre+3), f4=__ldg(fpre+4), f5=__ldg(fpre+5),
                f6=__ldg(fpre+6);
    const __half2 f0h=__float2half2_rn(f0), f1h=__float2half2_rn(f1),
                  f2h=__float2half2_rn(f2), f3h=__float2half2_rn(f3),
                  f4h=__float2half2_rn(f4), f5h=__float2half2_rn(f5),
                  f6h=__float2half2_rn(f6);
    float g[7];
#pragma unroll
    for (int i = 0; i < 7; i++) g[i] = __ldg(fpost + i);

    // ---- sM halo pads: colwords {0,1,2,3, 228..231} x 18 packs x 2 imgs ----
    for (int idx = t; idx < 2*PM*8; idx += NTHREADS) {
        int im = idx / (PM*8), rem = idx - im*(PM*8);
        int jm = rem >> 3, k = rem & 7;
        int c = (k < 4) ? k : 224 + k;
        sMh[im*M_WORDS + jm*WMS2 + swz(c)] = NEG2U;
    }

    if (t < 224) {
        const int img = t / 112;
        const int w   = t - 112*img;

        // ---- stage 1: vertical up-2 FIR -> half2 pack -> sA2 ----
        {
            const float* col = x + (size_t)(nc0 + img) * (WIN*WIN) + w;
            unsigned* sAc = sA2 + img*A_WORDS + (w + 1);
            float x0, x1, x2;
            { int r = in_row0;     x0 = (r>=0 && r<WIN) ? col[r*WIN] : 0.f; }
            { int r = in_row0 + 1; x1 = (r>=0 && r<WIN) ? col[r*WIN] : 0.f; }
            { int r = in_row0 + 2; x2 = (r>=0 && r<WIN) ? col[r*WIN] : 0.f; }
#pragma unroll
            for (int q = 0; q < 20; q++) {
                int r = in_row0 + q + 3;
                float x3 = (r>=0 && r<WIN) ? col[r*WIN] : 0.f;
                float ae = f1*x0 + f3*x1 + f5*x2;           // A row 2q
                float ao = f0*x0 + f2*x1 + f4*x2 + f6*x3;   // A row 2q+1
                __half2 h = __floats2half2_rn(ae, ao);
                sAc[q*WAS] = *(unsigned*)&h;
                x0 = x1; x1 = x2; x2 = x3;
            }
        }
        // sA2 halo zeros: words {0,113,114} x 20 packs x 2 imgs = 120
        for (int idx = t; idx < 120; idx += 224) {
            int im = idx / 60, rem = idx - 60*im;
            int q = rem / 3, k = rem - 3*q;
            sA2[im*A_WORDS + q*WAS + (k == 0 ? 0 : 112 + k)] = 0u;
        }
    }
    __syncthreads();

    // ---- stage 2: HFMA2 horizontal up-FIR + packed rolling 5-row max ----
    if (t < 224) {
        const int img = t / 112;
        const int w   = t - 112*img;
        const unsigned* ap = sA2 + img*A_WORDS + w;   // words w..w+3 = cols w-1..w+2
        unsigned* mrow = sMh + img*M_WORDS + swz(2*w + 4);  // col pair (2w,2w+1)
        const int vlo = (0 - u0) > 0 ? (0 - u0) : 0;        // even
        const int jlo = vlo >> 1;
        int jhi = (224 - u0) >> 1; if (jhi > 20) jhi = 20;
        __half2 PeP = NEG2, PoP = NEG2, AeP = NEG2, AoP = NEG2;
#pragma unroll
        for (int j = 0; j < 20; j++) {
            const unsigned* a = ap + j*WAS;
            __half2 a0=*(__half2*)&a[0], a1=*(__half2*)&a[1],
                    a2=*(__half2*)&a[2], a3=*(__half2*)&a[3];
            __half2 be = __hfma2(f5h,a2, __hfma2(f3h,a1, __hmul2(f1h,a0)));
            __half2 bo = __hfma2(f6h,a3, __hfma2(f4h,a2,
                          __hfma2(f2h,a1, __hmul2(f0h,a0))));
            bool valid = (j >= jlo) && (j < jhi);
            __half2 Pe = valid ? be : NEG2;
            __half2 Po = valid ? bo : NEG2;
            __half2 Ae = __hmax2(PeP, h2shift(PeP, Pe));
            __half2 Ao = __hmax2(PoP, h2shift(PoP, Po));
            if (j >= 2) {
                __half2 Me = __hmax2(AeP, __hmax2(Ae, Pe));
                __half2 Mo = __hmax2(AoP, __hmax2(Ao, Po));
                uint2 mm = make_uint2(*(unsigned*)&Me, *(unsigned*)&Mo);
                *reinterpret_cast<uint2*>(mrow + (j - 2)*WMS2) = mm;
            }
            AeP = Ae; AoP = Ao; PeP = Pe; PoP = Po;
        }
    }
    __syncthreads();

    // ---- edge fix-up: zero M rows with rg outside [0,222) (FIR zero-pad) ----
    {
        int btop = (-r0 > 0) ? -r0 : 0;                 // bad top rows: lc < btop
        int lc0 = 222 - r0; if (lc0 > 35) lc0 = 35;     // bad bottom: lc >= lc0
        if (btop > 0 || lc0 < 35) {
            for (int idx = t; idx < 2*WMS2; idx += NTHREADS) {
                int im = idx / WMS2, c = idx - WMS2*im;
                unsigned* Mi = sMh + im*M_WORDS;
                int cw = swz(c);
                for (int lc = 0; lc < btop; lc++)
                    ((unsigned short*)(Mi + (lc>>1)*WMS2 + cw))[lc & 1] = 0;
                for (int lc = lc0; lc < 35; lc++)
                    ((unsigned short*)(Mi + (lc>>1)*WMS2 + cw))[lc & 1] = 0;
            }
            __syncthreads();
        }
    }

    // ---- stage 3: packed 5-col max + vertical FIR + shfl horizontal FIR ----
    {
        const int wid = t >> 5, lane = t & 31;
        const int img = wid >> 2;                  // warps 0-3 img0, 4-7 img1
        const int lp  = wid & 3;                   // output rows 2lp, 2lp+1
        const int q   = (lane < 28) ? lane : 27;
        const unsigned* Mi = sMh + img*M_WORDS;
        float d0[8] = {0,0,0,0,0,0,0,0};
        float d1[8] = {0,0,0,0,0,0,0,0};
#pragma unroll
        for (int pp = 0; pp < 6; pp++) {
            const int pg = 4*lp + pp;
            const unsigned* base = Mi + pg*WMS2;
            unsigned Cw[16];
#pragma unroll
            for (int gi = 0; gi < 4; gi++) {
                uint4 v = *reinterpret_cast<const uint4*>(base + swz(8*q + 4*gi));
                Cw[4*gi+0] = v.x; Cw[4*gi+1] = v.y; Cw[4*gi+2] = v.z; Cw[4*gi+3] = v.w;
            }
            __half2 C[16];
#pragma unroll
            for (int i = 0; i < 16; i++) C[i] = *(__half2*)&Cw[i];
            __half2 p[10];                          // p[i-3] = max(C[i],C[i+1])
#pragma unroll
            for (int i = 0; i < 10; i++) p[i] = __hmax2(C[i+3], C[i+4]);
#pragma unroll
            for (int k = 0; k < 8; k++) {
                __half2 wmx = __hmax2(p[k], __hmax2(p[k+2], C[k+7]));
                float lo = __low2float(wmx);
                float hi = __high2float(wmx);
                // static tap schedule: rows rr = 2pp (lo), 2pp+1 (hi)
                if (pp == 0)      { d0[k] += g[0]*lo + g[1]*hi; }
                else if (pp == 1) { d0[k] += g[2]*lo + g[3]*hi; }
                else if (pp == 2) { d0[k] += g[4]*lo + g[5]*hi;
                                    d1[k] += g[0]*lo + g[1]*hi; }
                else if (pp == 3) { d0[k] += g[6]*lo;
                                    d1[k] += g[2]*lo + g[3]*hi; }
                else if (pp == 4) { d1[k] += g[4]*lo + g[5]*hi; }
                else              { d1[k] += g[6]*lo; }
            }
        }
        if (q == 27) { d0[6]=0.f; d0[7]=0.f; d1[6]=0.f; d1[7]=0.f; }  // D[222..223]=0

        // horizontal down-FIR: neighbor D cols via shfl_up
        float n5a = __shfl_up_sync(0xffffffffu, d0[5], 1);
        float n6a = __shfl_up_sync(0xffffffffu, d0[6], 1);
        float n7a = __shfl_up_sync(0xffffffffu, d0[7], 1);
        float n5b = __shfl_up_sync(0xffffffffu, d1[5], 1);
        float n6b = __shfl_up_sync(0xffffffffu, d1[6], 1);
        float n7b = __shfl_up_sync(0xffffffffu, d1[7], 1);
        if (q == 0) { n5a=0.f; n6a=0.f; n7a=0.f; n5b=0.f; n6b=0.f; n7b=0.f; }

        float oe0 = g[0]*n5a + g[1]*n6a + g[2]*n7a
                  + g[3]*d0[0] + g[4]*d0[1] + g[5]*d0[2] + g[6]*d0[3];
        float oo0 = g[0]*d0[1] + g[1]*d0[2] + g[2]*d0[3] + g[3]*d0[4]
                  + g[4]*d0[5] + g[5]*d0[6] + g[6]*d0[7];
        float oe1 = g[0]*n5b + g[1]*n6b + g[2]*n7b
                  + g[3]*d1[0] + g[4]*d1[1] + g[5]*d1[2] + g[6]*d1[3];
        float oo1 = g[0]*d1[1] + g[1]*d1[2] + g[2]*d1[3] + g[3]*d1[4]
                  + g[4]*d1[5] + g[5]*d1[6] + g[6]*d1[7];

        if (lane < 28) {
            float* ob = out + (size_t)(nc0 + img)*(HOUT*WOUT)
                            + (size_t)(i0 + 2*lp)*WOUT + 2*q;
            *reinterpret_cast<float2*>(ob)        = make_float2(oe0, oo0);
            *reinterpret_cast<float2*>(ob + WOUT) = make_float2(oe1, oo1);
        }
    }
}

extern "C" void kernel_launch(void* const* d_in, const int* in_sizes, int n_in,
                              void* d_out, int out_size)
{
    const float* x     = (const float*)d_in[0];   // (32,64,112,112)
    const float* fpre  = (const float*)d_in[1];   // (7,)
    const float* fpost = (const float*)d_in[2];   // (7,)
    float* out = (float*)d_out;                   // (32,64,56,56)

    const size_t smem_bytes = SMEM_WORDS * sizeof(unsigned); // 51968
    cudaFuncSetAttribute(aamaxpool_fused_kernel,
                         cudaFuncAttributeMaxDynamicSharedMemorySize,
                         (int)smem_bytes);

    dim3 grid(HOUT / TI, 32 * 64 / 2);   // 7 strips x 1024 image-pairs
    aamaxpool_fused_kernel<<<grid, NTHREADS, smem_bytes>>>(x, fpre, fpost, out);
}

// round 10
// speedup vs baseline: 1.4893x; 1.0267x over previous
#include <cuda_runtime.h>
#include <cuda_fp16.h>

// Fused AA max-pool: up2+FIR7 -> maxpool5x5 s1 -> FIR7+down4.
// One CTA = TWO (n,c) images x 8 output rows, 256 threads.
// Row-pair half2 packing through the whole pipeline; stages 1-2 are
// specialized on EDGE (blockIdx.x 0/6) vs interior (no bounds code at all).

#define WIN  112
#define TI   8
#define WAS  116                 // sA2: col c at word c+1 (c in [-1,113])
#define PA   20                  // A packs (rows 0..39)
#define A_WORDS (PA*WAS)         // 2320
#define WMS2 232                 // sM2 row stride (words); col v at word v+4
#define PM   18                  // M packs (rows 0..35)
#define M_WORDS (PM*WMS2)        // 4176
#define HOUT 56
#define WOUT 56
#define NTHREADS 256

#define OFF_M 0                          // 2 imgs x 4176 words
#define OFF_A (2*M_WORDS)                // 2 imgs x 2320 words
#define SMEM_WORDS (OFF_A + 2*A_WORDS)   // 12992 words = 51968 B -> 4 CTAs/SM

__device__ __forceinline__ int swz(int c) { return c ^ (((c >> 5) & 1) << 2); }

__device__ __forceinline__ __half2 h2shift(__half2 a, __half2 b) {
    unsigned r = __byte_perm(*(unsigned*)&a, *(unsigned*)&b, 0x5432);
    return *(__half2*)&r;
}

// ---- stages 1+2, templated on EDGE handling ----
template<bool EDGE>
__device__ __forceinline__ void stage12(
    unsigned* __restrict__ sA2, unsigned* __restrict__ sMh,
    const float* __restrict__ x, int nc0, int t,
    int in_row0, int u0,
    float f0, float f1, float f2, float f3, float f4, float f5, float f6,
    __half2 f0h, __half2 f1h, __half2 f2h, __half2 f3h,
    __half2 f4h, __half2 f5h, __half2 f6h)
{
    const unsigned NEG2U = 0xFC00FC00u;
    const __half2 NEG2 = *(const __half2*)&NEG2U;

    if (t < 224) {
        const int img = t / 112;
        const int w   = t - 112*img;

        // ---- stage 1: vertical up-2 FIR -> half2 pack -> sA2 ----
        {
            const float* col = x + (size_t)(nc0 + img) * (WIN*WIN) + w;
            unsigned* sAc = sA2 + img*A_WORDS + (w + 1);
            float x0, x1, x2;
            if (EDGE) {
                int r;
                r = in_row0;     x0 = (r>=0 && r<WIN) ? col[r*WIN] : 0.f;
                r = in_row0 + 1; x1 = (r>=0 && r<WIN) ? col[r*WIN] : 0.f;
                r = in_row0 + 2; x2 = (r>=0 && r<WIN) ? col[r*WIN] : 0.f;
            } else {
                x0 = col[in_row0*WIN];
                x1 = col[(in_row0+1)*WIN];
                x2 = col[(in_row0+2)*WIN];
            }
#pragma unroll
            for (int q = 0; q < 20; q++) {
                int r = in_row0 + q + 3;
                float x3;
                if (EDGE) x3 = (r>=0 && r<WIN) ? col[r*WIN] : 0.f;
                else      x3 = col[r*WIN];
                float ae = f1*x0 + f3*x1 + f5*x2;           // A row 2q
                float ao = f0*x0 + f2*x1 + f4*x2 + f6*x3;   // A row 2q+1
                __half2 h = __floats2half2_rn(ae, ao);
                sAc[q*WAS] = *(unsigned*)&h;
                x0 = x1; x1 = x2; x2 = x3;
            }
        }
        // sA2 halo zeros: words {0,113,114} x 20 packs x 2 imgs = 120
        for (int idx = t; idx < 120; idx += 224) {
            int im = idx / 60, rem = idx - 60*im;
            int q = rem / 3, k = rem - 3*q;
            sA2[im*A_WORDS + q*WAS + (k == 0 ? 0 : 112 + k)] = 0u;
        }
    }
    __syncthreads();

    // ---- stage 2: HFMA2 horizontal up-FIR + packed rolling 5-row max ----
    if (t < 224) {
        const int img = t / 112;
        const int w   = t - 112*img;
        const unsigned* ap = sA2 + img*A_WORDS + w;   // words = cols w-1..w+2
        unsigned* mrow = sMh + img*M_WORDS + swz(2*w + 4);
        int jlo = 0, jhi = 20;
        if (EDGE) {
            int v = (0 - u0) > 0 ? (0 - u0) : 0;
            jlo = v >> 1;
            jhi = (224 - u0) >> 1; if (jhi > 20) jhi = 20;
        }
        __half2 PeP = NEG2, PoP = NEG2, AeP = NEG2, AoP = NEG2;
#pragma unroll
        for (int j = 0; j < 20; j++) {
            const unsigned* a = ap + j*WAS;
            __half2 a0=*(__half2*)&a[0], a1=*(__half2*)&a[1],
                    a2=*(__half2*)&a[2], a3=*(__half2*)&a[3];
            __half2 be = __hfma2(f5h,a2, __hfma2(f3h,a1, __hmul2(f1h,a0)));
            __half2 bo = __hfma2(f6h,a3, __hfma2(f4h,a2,
                          __hfma2(f2h,a1, __hmul2(f0h,a0))));
            __half2 Pe, Po;
            if (EDGE) {
                bool valid = (j >= jlo) && (j < jhi);
                Pe = valid ? be : NEG2;
                Po = valid ? bo : NEG2;
            } else { Pe = be; Po = bo; }
            __half2 Ae = __hmax2(PeP, h2shift(PeP, Pe));
            __half2 Ao = __hmax2(PoP, h2shift(PoP, Po));
            if (j >= 2) {
                __half2 Me = __hmax2(AeP, __hmax2(Ae, Pe));
                __half2 Mo = __hmax2(AoP, __hmax2(Ao, Po));
                uint2 mm = make_uint2(*(unsigned*)&Me, *(unsigned*)&Mo);
                *reinterpret_cast<uint2*>(mrow + (j - 2)*WMS2) = mm;
            }
            AeP = Ae; AoP = Ao; PeP = Pe; PoP = Po;
        }
    }
    __syncthreads();
}

__global__ void __launch_bounds__(NTHREADS, 4)
aamaxpool_fused_kernel(const float* __restrict__ x,
                       const float* __restrict__ fpre,
                       const float* __restrict__ fpost,
                       float* __restrict__ out)
{
    extern __shared__ unsigned smu[];
    unsigned* sMh = smu + OFF_M;
    unsigned* sA2 = smu + OFF_A;

    const int t  = threadIdx.x;
    const int i0 = blockIdx.x * TI;
    const int nc0 = 2 * blockIdx.y;
    const int in_row0 = 2*i0 - 3;
    const int u0 = 4*i0 - 4;
    const int r0 = 4*i0 - 3;
    const unsigned NEG2U = 0xFC00FC00u;
    const bool edge = (blockIdx.x == 0) | (blockIdx.x == 6);

    const float f0=__ldg(fpre+0), f1=__ldg(fpre+1), f2=__ldg(fpre+2),
                f3=__ldg(fpre+3), f4=__ldg(fpre+4), f5=__ldg(fpre+5),
                f6=__ldg(fpre+6);
    const __half2 f0h=__float2half2_rn(f0), f1h=__float2half2_rn(f1),
                  f2h=__float2half2_rn(f2), f3h=__float2half2_rn(f3),
                  f4h=__float2half2_rn(f4), f5h=__float2half2_rn(f5),
                  f6h=__float2half2_rn(f6);
    float g[7];
#pragma unroll
    for (int i = 0; i < 7; i++) g[i] = __ldg(fpost + i);

    // ---- sM halo pads: colwords {0..3, 228..231} x 18 packs x 2 imgs ----
    for (int idx = t; idx < 2*PM*8; idx += NTHREADS) {
        int im = idx / (PM*8), rem = idx - im*(PM*8);
        int jm = rem >> 3, k = rem & 7;
        int c = (k < 4) ? k : 224 + k;
        sMh[im*M_WORDS + jm*WMS2 + swz(c)] = NEG2U;
    }

    if (edge) {
        stage12<true >(sA2, sMh, x, nc0, t, in_row0, u0,
                       f0,f1,f2,f3,f4,f5,f6, f0h,f1h,f2h,f3h,f4h,f5h,f6h);
        // edge fix-up: zero M rows with rg outside [0,222) (FIR zero-pad)
        int btop = (-r0 > 0) ? -r0 : 0;
        int lc0 = 222 - r0; if (lc0 > 35) lc0 = 35;
        if (btop > 0 || lc0 < 35) {
            for (int idx = t; idx < 2*WMS2; idx += NTHREADS) {
                int im = idx / WMS2, c = idx - WMS2*im;
                unsigned* Mi = sMh + im*M_WORDS;
                int cw = swz(c);
                for (int lc = 0; lc < btop; lc++)
                    ((unsigned short*)(Mi + (lc>>1)*WMS2 + cw))[lc & 1] = 0;
                for (int lc = lc0; lc < 35; lc++)
                    ((unsigned short*)(Mi + (lc>>1)*WMS2 + cw))[lc & 1] = 0;
            }
            __syncthreads();
        }
    } else {
        stage12<false>(sA2, sMh, x, nc0, t, in_row0, u0,
                       f0,f1,f2,f3,f4,f5,f6, f0h,f1h,f2h,f3h,f4h,f5h,f6h);
    }

    // ---- stage 3: packed 5-col max + vertical FIR + shfl horizontal FIR ----
    {
        const int wid = t >> 5, lane = t & 31;
        const int img = wid >> 2;                  // warps 0-3 img0, 4-7 img1
        const int lp  = wid & 3;                   // output rows 2lp, 2lp+1
        const int q   = (lane < 28) ? lane : 27;
        const unsigned* Mi = sMh + img*M_WORDS;
        float d0[8] = {0,0,0,0,0,0,0,0};
        float d1[8] = {0,0,0,0,0,0,0,0};
#pragma unroll
        for (int pp = 0; pp < 6; pp++) {
            const int pg = 4*lp + pp;
            const unsigned* base = Mi + pg*WMS2;
            unsigned Cw[16];
#pragma unroll
            for (int gi = 0; gi < 4; gi++) {
                uint4 v = *reinterpret_cast<const uint4*>(base + swz(8*q + 4*gi));
                Cw[4*gi+0] = v.x; Cw[4*gi+1] = v.y; Cw[4*gi+2] = v.z; Cw[4*gi+3] = v.w;
            }
            __half2 C[16];
#pragma unroll
            for (int i = 0; i < 16; i++) C[i] = *(__half2*)&Cw[i];
            __half2 p[10];                          // p[i-3] = max(C[i],C[i+1])
#pragma unroll
            for (int i = 0; i < 10; i++) p[i] = __hmax2(C[i+3], C[i+4]);
#pragma unroll
            for (int k = 0; k < 8; k++) {
                __half2 wmx = __hmax2(p[k], __hmax2(p[k+2], C[k+7]));
                float lo = __low2float(wmx);
                float hi = __high2float(wmx);
                if (pp == 0)      { d0[k] += g[0]*lo + g[1]*hi; }
                else if (pp == 1) { d0[k] += g[2]*lo + g[3]*hi; }
                else if (pp == 2) { d0[k] += g[4]*lo + g[5]*hi;
                                    d1[k] += g[0]*lo + g[1]*hi; }
                else if (pp == 3) { d0[k] += g[6]*lo;
                                    d1[k] += g[2]*lo + g[3]*hi; }
                else if (pp == 4) { d1[k] += g[4]*lo + g[5]*hi; }
                else              { d1[k] += g[6]*lo; }
            }
        }
        if (q == 27) { d0[6]=0.f; d0[7]=0.f; d1[6]=0.f; d1[7]=0.f; }

        float n5a = __shfl_up_sync(0xffffffffu, d0[5], 1);
        float n6a = __shfl_up_sync(0xffffffffu, d0[6], 1);
        float n7a = __shfl_up_sync(0xffffffffu, d0[7], 1);
        float n5b = __shfl_up_sync(0xffffffffu, d1[5], 1);
        float n6b = __shfl_up_sync(0xffffffffu, d1[6], 1);
        float n7b = __shfl_up_sync(0xffffffffu, d1[7], 1);
        if (q == 0) { n5a=0.f; n6a=0.f; n7a=0.f; n5b=0.f; n6b=0.f; n7b=0.f; }

        float oe0 = g[0]*n5a + g[1]*n6a + g[2]*n7a
                  + g[3]*d0[0] + g[4]*d0[1] + g[5]*d0[2] + g[6]*d0[3];
        float oo0 = g[0]*d0[1] + g[1]*d0[2] + g[2]*d0[3] + g[3]*d0[4]
                  + g[4]*d0[5] + g[5]*d0[6] + g[6]*d0[7];
        float oe1 = g[0]*n5b + g[1]*n6b + g[2]*n7b
                  + g[3]*d1[0] + g[4]*d1[1] + g[5]*d1[2] + g[6]*d1[3];
        float oo1 = g[0]*d1[1] + g[1]*d1[2] + g[2]*d1[3] + g[3]*d1[4]
                  + g[4]*d1[5] + g[5]*d1[6] + g[6]*d1[7];

        if (lane < 28) {
            float* ob = out + (size_t)(nc0 + img)*(HOUT*WOUT)
                            + (size_t)(i0 + 2*lp)*WOUT + 2*q;
            *reinterpret_cast<float2*>(ob)        = make_float2(oe0, oo0);
            *reinterpret_cast<float2*>(ob + WOUT) = make_float2(oe1, oo1);
        }
    }
}

extern "C" void kernel_launch(void* const* d_in, const int* in_sizes, int n_in,
                              void* d_out, int out_size)
{
    const float* x     = (const float*)d_in[0];   // (32,64,112,112)
    const float* fpre  = (const float*)d_in[1];   // (7,)
    const float* fpost = (const float*)d_in[2];   // (7,)
    float* out = (float*)d_out;                   // (32,64,56,56)

    const size_t smem_bytes = SMEM_WORDS * sizeof(unsigned); // 51968
    cudaFuncSetAttribute(aamaxpool_fused_kernel,
                         cudaFuncAttributeMaxDynamicSharedMemorySize,
                         (int)smem_bytes);

    dim3 grid(HOUT / TI, 32 * 64 / 2);   // 7 strips x 1024 image-pairs
    aamaxpool_fused_kernel<<<grid, NTHREADS, smem_bytes>>>(x, fpre, fpost, out);
}